// round 1
// baseline (speedup 1.0000x reference)
#include <cuda_runtime.h>

// Problem constants
#define BATCH 4096
#define SEQT  256
#define DIN   32
#define HID   64
#define GATES 256   // 4*HID
#define BT    32    // batch rows per CTA
#define NTHR  256
#define NCTA  (BATCH / BT)  // 128
#define ST    36    // padded row stride (floats) for transposed activation buffers

// ---- global scratch (transposed weights, fused biases), built by prep kernel ----
__device__ float g_W0t[HID * GATES];        // Whh0^T  [64][256]
__device__ float g_Wx0t[DIN * GATES];       // Wih0^T  [32][256]   (read per-step from L2)
__device__ float g_W1t[2 * HID * GATES];    // [Wih1; Whh1]^T [128][256]
__device__ float g_b0[GATES];
__device__ float g_b1[GATES];

__global__ void prep_kernel(const float* __restrict__ Wih0, const float* __restrict__ Whh0,
                            const float* __restrict__ bih0, const float* __restrict__ bhh0,
                            const float* __restrict__ Wih1, const float* __restrict__ Whh1,
                            const float* __restrict__ bih1, const float* __restrict__ bhh1)
{
    int idx = blockIdx.x * blockDim.x + threadIdx.x;
    int total = HID * GATES + DIN * GATES + 2 * HID * GATES + 2 * GATES;
    for (int i = idx; i < total; i += gridDim.x * blockDim.x) {
        if (i < HID * GATES) {
            int k = i / GATES, n = i % GATES;
            g_W0t[i] = Whh0[n * HID + k];
        } else if (i < HID * GATES + DIN * GATES) {
            int j = i - HID * GATES;
            int k = j / GATES, n = j % GATES;
            g_Wx0t[j] = Wih0[n * DIN + k];
        } else if (i < HID * GATES + DIN * GATES + 2 * HID * GATES) {
            int j = i - HID * GATES - DIN * GATES;
            int k = j / GATES, n = j % GATES;
            g_W1t[j] = (k < HID) ? Wih1[n * HID + k] : Whh1[n * HID + (k - HID)];
        } else {
            int j = i - (HID * GATES + DIN * GATES + 2 * HID * GATES);
            if (j < GATES) g_b0[j] = bih0[j] + bhh0[j];
            else           g_b1[j - GATES] = bih1[j - GATES] + bhh1[j - GATES];
        }
    }
}

// ---- packed f32x2 helpers ----
__device__ __forceinline__ unsigned long long fma2(unsigned long long a, unsigned long long b,
                                                   unsigned long long c) {
    unsigned long long d;
    asm("fma.rn.f32x2 %0, %1, %2, %3;" : "=l"(d) : "l"(a), "l"(b), "l"(c));
    return d;
}
__device__ __forceinline__ unsigned long long dup2(float x) {
    unsigned long long d;
    asm("mov.b64 %0, {%1, %1};" : "=l"(d) : "f"(x));
    return d;
}
__device__ __forceinline__ float2 unpack2(unsigned long long v) {
    float2 f;
    asm("mov.b64 {%0, %1}, %2;" : "=f"(f.x), "=f"(f.y) : "l"(v));
    return f;
}

// ---- fast, accurate-enough activations (MUFU EX2/RCP: ~1e-7 rel err) ----
__device__ __forceinline__ float fast_ex2(float x) {
    float y; asm("ex2.approx.f32 %0, %1;" : "=f"(y) : "f"(x)); return y;
}
__device__ __forceinline__ float fast_rcp(float x) {
    float y; asm("rcp.approx.f32 %0, %1;" : "=f"(y) : "f"(x)); return y;
}
__device__ __forceinline__ float sigf(float x) {
    return fast_rcp(1.0f + fast_ex2(-1.4426950408889634f * x));
}
__device__ __forceinline__ float tanhf_fast(float x) {
    x = fminf(fmaxf(x, -15.0f), 15.0f);           // avoid inf*0 = NaN in extreme tails
    float e = fast_ex2(-2.8853900817779268f * x); // exp(-2x)
    return (1.0f - e) * fast_rcp(1.0f + e);
}

// Inner GEMM fragment: acc[m][g] (f32x2 over cell pair) += in^T[k][m0..m0+3] * Wt[k][g*64+u0..+1]
template <bool GLOBAL_W, int K>
__device__ __forceinline__ void gemm_part(const float* __restrict__ inT,
                                          const float* __restrict__ Wt,
                                          int m0, int u0,
                                          unsigned long long acc[4][4])
{
#pragma unroll 8
    for (int k = 0; k < K; k++) {
        float4 hv = *(const float4*)(inT + k * ST + m0);
        unsigned long long w[4];
#pragma unroll
        for (int g = 0; g < 4; g++) {
            const float* wp = Wt + k * GATES + g * HID + u0;
            if (GLOBAL_W) w[g] = __ldg((const unsigned long long*)wp);
            else          w[g] = *(const unsigned long long*)wp;
        }
        unsigned long long a;
        a = dup2(hv.x);
#pragma unroll
        for (int g = 0; g < 4; g++) acc[0][g] = fma2(a, w[g], acc[0][g]);
        a = dup2(hv.y);
#pragma unroll
        for (int g = 0; g < 4; g++) acc[1][g] = fma2(a, w[g], acc[1][g]);
        a = dup2(hv.z);
#pragma unroll
        for (int g = 0; g < 4; g++) acc[2][g] = fma2(a, w[g], acc[2][g]);
        a = dup2(hv.w);
#pragma unroll
        for (int g = 0; g < 4; g++) acc[3][g] = fma2(a, w[g], acc[3][g]);
    }
}

// activations + cell update + write h (transposed) for one layer
__device__ __forceinline__ void lstm_update(unsigned long long acc[4][4], float* __restrict__ cr,
                                            float* __restrict__ hT, int m0, int u0)
{
    float hn0[4], hn1[4];
#pragma unroll
    for (int m = 0; m < 4; m++) {
        float2 pi = unpack2(acc[m][0]);
        float2 pf = unpack2(acc[m][1]);
        float2 pg = unpack2(acc[m][2]);
        float2 po = unpack2(acc[m][3]);
        {
            float iv = sigf(pi.x), fv = sigf(pf.x), gv = tanhf_fast(pg.x), ov = sigf(po.x);
            float c = fv * cr[m * 2 + 0] + iv * gv;
            cr[m * 2 + 0] = c;
            hn0[m] = ov * tanhf_fast(c);
        }
        {
            float iv = sigf(pi.y), fv = sigf(pf.y), gv = tanhf_fast(pg.y), ov = sigf(po.y);
            float c = fv * cr[m * 2 + 1] + iv * gv;
            cr[m * 2 + 1] = c;
            hn1[m] = ov * tanhf_fast(c);
        }
    }
    *(float4*)(hT + (u0 + 0) * ST + m0) = make_float4(hn0[0], hn0[1], hn0[2], hn0[3]);
    *(float4*)(hT + (u0 + 1) * ST + m0) = make_float4(hn1[0], hn1[1], hn1[2], hn1[3]);
}

// Shared layout (floats)
#define OFF_W0   0
#define OFF_W1   (OFF_W0 + HID * GATES)          // 16384
#define OFF_B0   (OFF_W1 + 2 * HID * GATES)      // +32768
#define OFF_B1   (OFF_B0 + GATES)
#define OFF_H0T  (OFF_B1 + GATES)
#define OFF_H1T  (OFF_H0T + HID * ST)
#define OFF_XT   (OFF_H1T + HID * ST)
#define SMEM_FLOATS (OFF_XT + DIN * ST)          // 55424 floats = 221696 B

__global__ void __launch_bounds__(NTHR, 1)
lstm_fused_kernel(const float* __restrict__ x,
                  const float* __restrict__ W1h, const float* __restrict__ b1h,
                  const float* __restrict__ W2h, const float* __restrict__ b2h,
                  float* __restrict__ out)
{
    extern __shared__ float smem[];
    float* sW0 = smem + OFF_W0;
    float* sW1 = smem + OFF_W1;
    float* sb0 = smem + OFF_B0;
    float* sb1 = smem + OFF_B1;
    float* h0T = smem + OFF_H0T;
    float* h1T = smem + OFF_H1T;
    float* xT  = smem + OFF_XT;

    const int tid = threadIdx.x;
    const int b0  = blockIdx.x * BT;

    // load weights into shared (float4 copies)
    {
        const float4* src0 = (const float4*)g_W0t;
        float4* dst0 = (float4*)sW0;
        for (int i = tid; i < HID * GATES / 4; i += NTHR) dst0[i] = src0[i];
        const float4* src1 = (const float4*)g_W1t;
        float4* dst1 = (float4*)sW1;
        for (int i = tid; i < 2 * HID * GATES / 4; i += NTHR) dst1[i] = src1[i];
        if (tid < GATES) { sb0[tid] = g_b0[tid]; sb1[tid] = g_b1[tid]; }
        // zero state buffers
        for (int i = tid; i < 2 * HID * ST; i += NTHR) h0T[i] = 0.0f;  // covers h0T and h1T
    }

    const int gm = tid & 7;        // 8 m-groups
    const int gn = tid >> 3;       // 32 cell-pair groups
    const int m0 = gm * 4;
    const int u0 = gn * 2;

    float c0r[8], c1r[8];
#pragma unroll
    for (int i = 0; i < 8; i++) { c0r[i] = 0.0f; c1r[i] = 0.0f; }

    // x prefetch setup: thread loads one float4 of row (tid>>3), d-chunk (tid&7)
    const int xm = tid >> 3;       // 0..31
    const int xd = tid & 7;        // 0..7
    const float* xptr = x + (size_t)(b0 + xm) * SEQT * DIN + xd * 4;
    float4 xv = *(const float4*)(xptr);  // t = 0

    __syncthreads();

    for (int t = 0; t < SEQT; t++) {
        // A: stage x_t (transposed), prefetch x_{t+1}
        xT[(4 * xd + 0) * ST + xm] = xv.x;
        xT[(4 * xd + 1) * ST + xm] = xv.y;
        xT[(4 * xd + 2) * ST + xm] = xv.z;
        xT[(4 * xd + 3) * ST + xm] = xv.w;
        if (t + 1 < SEQT) xv = *(const float4*)(xptr + (size_t)(t + 1) * DIN);
        __syncthreads();

        // C: layer 0 gemm: K = 64 (h0, Whh0 smem) + 32 (x, Wih0 global/L2)
        unsigned long long acc[4][4];
#pragma unroll
        for (int g = 0; g < 4; g++) {
            unsigned long long bp = *(const unsigned long long*)(&sb0[g * HID + u0]);
            acc[0][g] = bp; acc[1][g] = bp; acc[2][g] = bp; acc[3][g] = bp;
        }
        gemm_part<false, HID>(h0T, sW0, m0, u0, acc);
        gemm_part<true,  DIN>(xT, g_Wx0t, m0, u0, acc);
        __syncthreads();

        // D: layer 0 activations, write new h0
        lstm_update(acc, c0r, h0T, m0, u0);
        __syncthreads();

        // E: layer 1 gemm: K = 64 (h0 new, Wih1) + 64 (h1 prev, Whh1)
#pragma unroll
        for (int g = 0; g < 4; g++) {
            unsigned long long bp = *(const unsigned long long*)(&sb1[g * HID + u0]);
            acc[0][g] = bp; acc[1][g] = bp; acc[2][g] = bp; acc[3][g] = bp;
        }
        gemm_part<false, HID>(h0T, sW1, m0, u0, acc);
        gemm_part<false, HID>(h1T, sW1 + HID * GATES, m0, u0, acc);
        __syncthreads();

        // F: layer 1 activations, write new h1
        lstm_update(acc, c1r, h1T, m0, u0);
        // (no barrier needed: next-iter writes only touch xT; barrier B orders h1T)
        __syncthreads();
    }

    // ---- head: f = relu(h1_last @ W1^T + b1); out = f @ W2^T + b2 ----
    // stage W1 head (64x64) into sW0 region
    for (int i = tid; i < HID * HID; i += NTHR) sW0[i] = W1h[i];
    __syncthreads();

    float* sF = h0T;  // reuse: [64][33]
    {
        const int u = tid & 63;
        const int mbase = (tid >> 6) * 8;
        float bias = b1h[u];
#pragma unroll
        for (int mm = 0; mm < 8; mm++) {
            int m = mbase + mm;
            float s = bias;
#pragma unroll 8
            for (int k = 0; k < HID; k++) s += h1T[k * ST + m] * sW0[u * HID + k];
            sF[u * 33 + m] = fmaxf(s, 0.0f);
        }
    }
    __syncthreads();

    if (tid < BT) {
        float s = b2h[0];
#pragma unroll 8
        for (int u = 0; u < HID; u++) s += sF[u * 33 + tid] * __ldg(&W2h[u]);
        out[b0 + tid] = s;
    }
}

extern "C" void kernel_launch(void* const* d_in, const int* in_sizes, int n_in,
                              void* d_out, int out_size)
{
    const float* x    = (const float*)d_in[0];
    const float* Wih0 = (const float*)d_in[1];
    const float* Whh0 = (const float*)d_in[2];
    const float* bih0 = (const float*)d_in[3];
    const float* bhh0 = (const float*)d_in[4];
    const float* Wih1 = (const float*)d_in[5];
    const float* Whh1 = (const float*)d_in[6];
    const float* bih1 = (const float*)d_in[7];
    const float* bhh1 = (const float*)d_in[8];
    const float* W1   = (const float*)d_in[9];
    const float* b1   = (const float*)d_in[10];
    const float* W2   = (const float*)d_in[11];
    const float* b2   = (const float*)d_in[12];

    prep_kernel<<<64, 256>>>(Wih0, Whh0, bih0, bhh0, Wih1, Whh1, bih1, bhh1);

    size_t smem_bytes = (size_t)SMEM_FLOATS * sizeof(float);  // 221696 B
    cudaFuncSetAttribute(lstm_fused_kernel,
                         cudaFuncAttributeMaxDynamicSharedMemorySize, (int)smem_bytes);
    lstm_fused_kernel<<<NCTA, NTHR, smem_bytes>>>(x, W1, b1, W2, b2, (float*)d_out);
}